// round 5
// baseline (speedup 1.0000x reference)
#include <cuda_runtime.h>
#include <cuda_bf16.h>
#include <mma.h>

using namespace nvcuda;

#define B_    16
#define N_    1024
#define M_    1024
#define D_    512
#define NDIAG 2047
#define LOG2E 1.4426950408889634f
#define LN2   0.6931471805599453f
#define NEGW  -1.0e9f
#define STRIPS 8
#define SROWS  128

// ---------------- device scratch ----------------
__device__ __nv_bfloat16 g_zx[(size_t)B_ * N_ * D_];
__device__ __nv_bfloat16 g_zy[(size_t)B_ * M_ * D_];
__device__ float g_theta[(size_t)B_ * NDIAG * 1024 + 8 * 1024];  // diag-major + 8-diag pad
__device__ float g_gpart[B_][8];
__device__ float g_bound[B_][STRIPS][2048];
__device__ int   g_prog[B_][STRIPS];

// ---------------- intrinsics ----------------
__device__ __forceinline__ float ex2f_(float x) {
    float y; asm("ex2.approx.ftz.f32 %0, %1;" : "=f"(y) : "f"(x)); return y;
}
__device__ __forceinline__ float lg2f_(float x) {
    float y; asm("lg2.approx.ftz.f32 %0, %1;" : "=f"(y) : "f"(x)); return y;
}
__device__ __forceinline__ int ld_acq(const int* p) {
    int v; asm volatile("ld.acquire.gpu.b32 %0, [%1];" : "=r"(v) : "l"(p) : "memory"); return v;
}
__device__ __forceinline__ void st_rel(int* p, int v) {
    asm volatile("st.release.gpu.b32 [%0], %1;" :: "l"(p), "r"(v) : "memory");
}
__device__ __forceinline__ int ld_acq_cta(const int* p) {
    int v; asm volatile("ld.acquire.cta.b32 %0, [%1];" : "=r"(v) : "l"(p) : "memory"); return v;
}
__device__ __forceinline__ void st_rel_cta(int* p, int v) {
    asm volatile("st.release.cta.b32 [%0], %1;" :: "l"(p), "r"(v) : "memory");
}

// ---------------- 1) fused fp32->bf16 convert + gap partial reduce ----------------
__global__ void __launch_bounds__(512) convgap_kernel(const float* __restrict__ zx,
                                                      const float* __restrict__ zy,
                                                      const float* __restrict__ gw) {
    int blk = blockIdx.x;           // row block 0..7 (128 rows)
    int b   = blockIdx.y;
    int c   = threadIdx.x;          // feature 0..511
    if (blk == 0 && b == 0 && c < B_ * STRIPS) ((int*)g_prog)[c] = -1;  // reset flags

    size_t base = ((size_t)b * N_ + (size_t)blk * 128) * D_ + c;
    const float* px = zx + base;
    const float* py = zy + base;
    __nv_bfloat16* qx = g_zx + base;
    __nv_bfloat16* qy = g_zy + base;
    float sx = 0.f, sy = 0.f;
#pragma unroll 4
    for (int r = 0; r < 128; r++) {
        float vx = px[(size_t)r * D_];
        float vy = py[(size_t)r * D_];
        qx[(size_t)r * D_] = __float2bfloat16(vx);
        qy[(size_t)r * D_] = __float2bfloat16(vy);
        sx += vx; sy += vy;
    }
    float v = sx * (1.0f / N_) * gw[c] + sy * (1.0f / M_) * gw[512 + c];
    __shared__ float red[512];
    red[c] = v;
    __syncthreads();
    for (int st = 256; st > 0; st >>= 1) {
        if (c < st) red[c] += red[c + st];
        __syncthreads();
    }
    if (c == 0) g_gpart[b][blk] = red[0];
}

// ---------------- 2) GEMM theta = zx @ zy^T, bf16 WMMA, smem staged, diag epilogue ----------------
__global__ void __launch_bounds__(256) gemm_kernel() {
    __shared__ __align__(16) __nv_bfloat16 sm[2][128 * 72];

    int b  = blockIdx.z;
    int I0 = blockIdx.y * 128;
    int J0 = blockIdx.x * 128;
    const __nv_bfloat16* Ag = g_zx + ((size_t)b * N_ + I0) * D_;
    const __nv_bfloat16* Bg = g_zy + ((size_t)b * M_ + J0) * D_;

    int warpId = threadIdx.x >> 5;
    int wr = warpId & 3;
    int wc = warpId >> 2;

    wmma::fragment<wmma::accumulator, 16, 16, 16, float> acc[2][4];
#pragma unroll
    for (int i = 0; i < 2; i++)
#pragma unroll
        for (int j = 0; j < 4; j++) wmma::fill_fragment(acc[i][j], 0.0f);

    wmma::fragment<wmma::matrix_a, 16, 16, 16, __nv_bfloat16, wmma::row_major> af[2];
    wmma::fragment<wmma::matrix_b, 16, 16, 16, __nv_bfloat16, wmma::col_major> bfr[4];

    int lr  = threadIdx.x >> 3;
    int lcq = threadIdx.x & 7;

    for (int kc = 0; kc < D_; kc += 64) {
#pragma unroll
        for (int p = 0; p < 4; p++) {
            int row = lr + p * 32;
            *(uint4*)&sm[0][row * 72 + lcq * 8] =
                *(const uint4*)&Ag[(size_t)row * D_ + kc + lcq * 8];
            *(uint4*)&sm[1][row * 72 + lcq * 8] =
                *(const uint4*)&Bg[(size_t)row * D_ + kc + lcq * 8];
        }
        __syncthreads();
#pragma unroll
        for (int kk = 0; kk < 64; kk += 16) {
#pragma unroll
            for (int i = 0; i < 2; i++)
                wmma::load_matrix_sync(af[i], &sm[0][(wr * 32 + i * 16) * 72 + kk], 72);
#pragma unroll
            for (int j = 0; j < 4; j++)
                wmma::load_matrix_sync(bfr[j], &sm[1][(wc * 64 + j * 16) * 72 + kk], 72);
#pragma unroll
            for (int i = 0; i < 2; i++)
#pragma unroll
                for (int j = 0; j < 4; j++)
                    wmma::mma_sync(acc[i][j], af[i], bfr[j], acc[i][j]);
        }
        __syncthreads();
    }

    float* tile = (float*)&sm[0][0];
    for (int phase = 0; phase < 2; phase++) {
        if ((wr >> 1) == phase) {
            int lrr = (wr & 1) * 32;
#pragma unroll
            for (int i = 0; i < 2; i++)
#pragma unroll
                for (int j = 0; j < 4; j++)
                    wmma::store_matrix_sync(tile + (size_t)(lrr + i * 16) * 128 + wc * 64 + j * 16,
                                            acc[i][j], 128, wmma::mem_row_major);
        }
        __syncthreads();
        int rowoff = phase * 64;
        for (int e = threadIdx.x; e < 191 * 64; e += 256) {
            int dl = e >> 6;
            int t  = e & 63;
            int li = (dl > 127 ? dl - 127 : 0) + t;
            int lj = dl - li;
            if (li < 64 && lj >= 0 && lj < 128) {
                int gi = I0 + rowoff + li;
                int gj = J0 + lj;
                g_theta[((size_t)b * NDIAG + (gi + gj)) * 1024 + gi] = tile[li * 128 + lj] * LOG2E;
            }
        }
        __syncthreads();
    }
}

// ---------------- 3) shuffle-wavefront DP ----------------
// CTA = 4 warps x 32 rows (strip of 128 rows). In-warp neighbor via shfl_up (no barrier).
// Warp->warp via full smem boundary arrays + cta release/acquire flags (every 8 diags).
// Strip->strip via g_bound/g_prog, 16-diag register chunks, one chunk prefetch ahead.
__global__ void __launch_bounds__(128) dp_kernel(const float* __restrict__ gb,
                                                 float* __restrict__ out) {
    const int s = blockIdx.x, b = blockIdx.y;
    const int t = threadIdx.x, w = t >> 5, lane = t & 31;
    const int r0 = s * SROWS;
    const int w0 = r0 + w * 32;

    __shared__ float sB[3][1060];
    __shared__ int   sF[3];
    __shared__ float sA;
    for (int k = t; k < 3 * 1060; k += 128) (&sB[0][0])[k] = NEGW;
    if (t < 3) sF[t] = -1;
    if (t == 0) {
        float a = 0.f;
#pragma unroll
        for (int k = 0; k < 8; k++) a += g_gpart[b][k];
        sA = (a + gb[0]) * LOG2E;
    }
    __syncthreads();

    const float A = sA, A2 = A + A;

    // theta: diag-major, 8-deep register prefetch ring
    const float* pf = g_theta + (size_t)b * NDIAG * 1024 + (size_t)w0 * 1024 + (w0 + lane);
    float thr[8];
#pragma unroll
    for (int u = 0; u < 8; u++) thr[u] = pf[(size_t)u * 1024];
    pf += 8 * 1024;

    const bool cs = (w > 0);                 // consume smem boundary
    const bool cg = (w == 0 && s > 0);       // consume global boundary
    const bool ps = (w < 3);                 // produce smem boundary
    const bool pg = (w == 3 && s < STRIPS - 1);

    const float* sIn = sB[(w > 0) ? (w - 1) : 0];
    const int*   fIn = &sF[(w > 0) ? (w - 1) : 0];
    float* sOut = sB[(w < 3) ? w : 0];
    int*   fOut = &sF[(w < 3) ? w : 0];
    const float* gsrc = &g_bound[b][(s > 0) ? (s - 1) : 0][0];
    const int*   gfin = &g_prog[b][(s > 0) ? (s - 1) : 0];
    float* gdst  = &g_bound[b][s][0];
    int*   gfout = &g_prog[b][s];
    const int bend = w0 + 1022;              // last real boundary diag from producer

    float bufA = NEGW, bufB = NEGW;          // global boundary chunks (even/odd)
    int gcache = -0x7FFFFFF0;
    int scache = -0x7FFFFFF0;

    // chunk fetch: lanes 0..15 hold diags [w0+16*c16-1 .. +15]
    auto gfetch = [&](int c16) -> float {
        int basei = w0 + 16 * c16 - 1;
        float v = NEGW;
        if (basei <= bend) {
            int tgt = min(basei + 15, bend);
            while (gcache < tgt) gcache = ld_acq(gfin);
            int d = basei + lane;
            if (lane < 16 && d <= bend) v = __ldcg(gsrc + d);
        }
        return v;
    };

    float bnd = NEGW;
    if (cg) {
        bufA = gfetch(0);
        bnd = __shfl_sync(0xffffffffu, bufA, 0);
    }

    float my_prev = NEGW;
    float nb_prev = (s == 0 && w == 0 && lane == 0) ? 0.0f : NEGW;

#define DP_MATH(THV, P)                                                     \
    {                                                                       \
        float nb = __shfl_up_sync(0xffffffffu, my_prev, 1);                 \
        if (lane == 0) nb = bnd;                                            \
        float h  = fmaxf(nb, my_prev);                                      \
        float l  = fminf(nb, my_prev);                                      \
        float m  = fmaxf(h + A, nb_prev);                                   \
        float lo = fminf(l + A, nb_prev);                                   \
        float mid = ((h + l) + A2) + (nb_prev - m) - lo;                    \
        float sf = 1.0f + ex2f_(lo - m) + ex2f_(mid - m);                   \
        float val = ((THV) + m) + lg2f_(sf);                                \
        val = ((unsigned)((P) - lane) <= 1023u) ? val : NEGW;               \
        nb_prev = nb;                                                       \
        my_prev = val;                                                      \
    }

#define DP_STEP(P, K)                                                       \
    {                                                                       \
        float bnew;                                                         \
        if (cs) bnew = sIn[(P) + 1];                                        \
        else if (cg) {                                                      \
            int pn = (P) + 1;                                               \
            float bsel = ((pn >> 4) & 1) ? bufB : bufA;                     \
            bnew = __shfl_sync(0xffffffffu, bsel, pn & 15);                 \
        } else bnew = NEGW;                                                 \
        float thv = thr[0];                                                 \
        float thn = pf[0]; pf += 1024;                                      \
        DP_MATH(thv, P)                                                     \
        if (ps && lane == 31) {                                             \
            if ((unsigned)((P) - 31) <= 1023u) sOut[(P) - 31] = my_prev;    \
            if ((K) == 7) st_rel_cta(fOut, (P) - 31);                       \
        }                                                                   \
        if (pg && lane == 31) {                                             \
            if ((unsigned)((P) - 31) <= 1023u) __stcg(gdst + w0 + (P), my_prev); \
            if ((K) == 7) st_rel(gfout, w0 + (P));                          \
        }                                                                   \
        bnd = bnew;                                                         \
        thr[0] = thr[1]; thr[1] = thr[2]; thr[2] = thr[3]; thr[3] = thr[4]; \
        thr[4] = thr[5]; thr[5] = thr[6]; thr[6] = thr[7]; thr[7] = thn;    \
    }

    // main: 131 chunks of 8 steps (p = 0..1047)
    for (int c8 = 0; c8 < 131; c8++) {
        if (cs) {
            int tgt = min(8 * c8 + 8, 1023);
            while (scache < tgt) scache = ld_acq_cta(fIn);
            if (c8 == 0) bnd = sIn[0];
        }
        if (cg && (c8 & 1) == 0) {
            int c16 = c8 >> 1;
            float v = gfetch(c16 + 1);
            if ((c16 + 1) & 1) bufB = v; else bufA = v;
        }
        int p0 = 8 * c8;
#pragma unroll
        for (int k = 0; k < 8; k++) {
            DP_STEP(p0 + k, k)
        }
    }
    // tail: p = 1048..1054 (boundary offsets needed here are all > 1023 -> init NEGW / masked)
    if (cs) { while (scache < 1023) scache = ld_acq_cta(fIn); }
#pragma unroll
    for (int k = 0; k < 7; k++) {
        DP_STEP(1048 + k, k)
    }
#undef DP_STEP
#undef DP_MATH

    if (ps && lane == 31) st_rel_cta(fOut, 4096);
    if (pg && lane == 31) st_rel(gfout, 0x7FFFFFF0);

    // strip 7, warp 3, lane 31: diag 2046 -> V[N][M]
    if (s == STRIPS - 1 && w == 3 && lane == 31) out[b] = my_prev * LN2;
}

// ---------------- launch ----------------
extern "C" void kernel_launch(void* const* d_in, const int* in_sizes, int n_in,
                              void* d_out, int out_size) {
    (void)in_sizes; (void)n_in; (void)out_size;
    const float* zx = (const float*)d_in[0];
    const float* zy = (const float*)d_in[1];
    const float* gw = (const float*)d_in[2];
    const float* gb = (const float*)d_in[3];
    float* out = (float*)d_out;

    convgap_kernel<<<dim3(8, B_), 512>>>(zx, zy, gw);
    gemm_kernel<<<dim3(8, 8, B_), 256>>>();
    dp_kernel<<<dim3(STRIPS, B_), 128>>>(gb, out);
}

// round 7
// speedup vs baseline: 1.2244x; 1.2244x over previous
#include <cuda_runtime.h>
#include <cuda_bf16.h>
#include <mma.h>
#include <cstdint>

using namespace nvcuda;

#define B_    16
#define N_    1024
#define M_    1024
#define D_    512
#define NDIAG 2047
#define LOG2E 1.4426950408889634f
#define LN2   0.6931471805599453f
#define NEGW  -1.0e9f
#define STRIPS 8
#define SROWS  128

// ---------------- device scratch ----------------
__device__ __nv_bfloat16 g_zx[(size_t)B_ * N_ * D_];
__device__ __nv_bfloat16 g_zy[(size_t)B_ * M_ * D_];
// theta in bf16, diag-major [b][d][i], pre-scaled by log2e; +128 diag pad for prefetch
__device__ __nv_bfloat16 g_theta_bf[((size_t)B_ * NDIAG + 128) * 1024];
__device__ float g_gpart[B_][8];
__device__ float g_bound[B_][STRIPS][2048];
__device__ int   g_prog[B_][STRIPS];

// ---------------- intrinsics ----------------
__device__ __forceinline__ float ex2f_(float x) {
    float y; asm("ex2.approx.ftz.f32 %0, %1;" : "=f"(y) : "f"(x)); return y;
}
__device__ __forceinline__ float lg2f_(float x) {
    float y; asm("lg2.approx.ftz.f32 %0, %1;" : "=f"(y) : "f"(x)); return y;
}
__device__ __forceinline__ int ld_acq(const int* p) {
    int v; asm volatile("ld.acquire.gpu.b32 %0, [%1];" : "=r"(v) : "l"(p) : "memory"); return v;
}
__device__ __forceinline__ void st_rel(int* p, int v) {
    asm volatile("st.release.gpu.b32 [%0], %1;" :: "l"(p), "r"(v) : "memory");
}
__device__ __forceinline__ int ld_acq_cta(const int* p) {
    int v; asm volatile("ld.acquire.cta.b32 %0, [%1];" : "=r"(v) : "l"(p) : "memory"); return v;
}
__device__ __forceinline__ void st_rel_cta(int* p, int v) {
    asm volatile("st.release.cta.b32 [%0], %1;" :: "l"(p), "r"(v) : "memory");
}
__device__ __forceinline__ void cpasync16(unsigned int dst, const void* src) {
    asm volatile("cp.async.cg.shared.global [%0], [%1], 16;" :: "r"(dst), "l"(src));
}

// ---------------- 1) fused fp32->bf16 convert + gap partial reduce ----------------
__global__ void __launch_bounds__(512) convgap_kernel(const float* __restrict__ zx,
                                                      const float* __restrict__ zy,
                                                      const float* __restrict__ gw) {
    int blk = blockIdx.x;
    int b   = blockIdx.y;
    int c   = threadIdx.x;
    if (blk == 0 && b == 0 && c < B_ * STRIPS) ((int*)g_prog)[c] = -1;

    size_t base = ((size_t)b * N_ + (size_t)blk * 128) * D_ + c;
    const float* px = zx + base;
    const float* py = zy + base;
    __nv_bfloat16* qx = g_zx + base;
    __nv_bfloat16* qy = g_zy + base;
    float sx = 0.f, sy = 0.f;
#pragma unroll 4
    for (int r = 0; r < 128; r++) {
        float vx = px[(size_t)r * D_];
        float vy = py[(size_t)r * D_];
        qx[(size_t)r * D_] = __float2bfloat16(vx);
        qy[(size_t)r * D_] = __float2bfloat16(vy);
        sx += vx; sy += vy;
    }
    float v = sx * (1.0f / N_) * gw[c] + sy * (1.0f / M_) * gw[512 + c];
    __shared__ float red[512];
    red[c] = v;
    __syncthreads();
    for (int st = 256; st > 0; st >>= 1) {
        if (c < st) red[c] += red[c + st];
        __syncthreads();
    }
    if (c == 0) g_gpart[b][blk] = red[0];
}

// ---------------- 2) GEMM theta = zx @ zy^T, bf16 WMMA, smem staged, bf16 diag epilogue ----
__global__ void __launch_bounds__(256) gemm_kernel() {
    __shared__ __align__(16) __nv_bfloat16 sm[2][128 * 72];

    int b  = blockIdx.z;
    int I0 = blockIdx.y * 128;
    int J0 = blockIdx.x * 128;
    const __nv_bfloat16* Ag = g_zx + ((size_t)b * N_ + I0) * D_;
    const __nv_bfloat16* Bg = g_zy + ((size_t)b * M_ + J0) * D_;

    int warpId = threadIdx.x >> 5;
    int wr = warpId & 3;
    int wc = warpId >> 2;

    wmma::fragment<wmma::accumulator, 16, 16, 16, float> acc[2][4];
#pragma unroll
    for (int i = 0; i < 2; i++)
#pragma unroll
        for (int j = 0; j < 4; j++) wmma::fill_fragment(acc[i][j], 0.0f);

    wmma::fragment<wmma::matrix_a, 16, 16, 16, __nv_bfloat16, wmma::row_major> af[2];
    wmma::fragment<wmma::matrix_b, 16, 16, 16, __nv_bfloat16, wmma::col_major> bfr[4];

    int lr  = threadIdx.x >> 3;
    int lcq = threadIdx.x & 7;

    for (int kc = 0; kc < D_; kc += 64) {
#pragma unroll
        for (int p = 0; p < 4; p++) {
            int row = lr + p * 32;
            *(uint4*)&sm[0][row * 72 + lcq * 8] =
                *(const uint4*)&Ag[(size_t)row * D_ + kc + lcq * 8];
            *(uint4*)&sm[1][row * 72 + lcq * 8] =
                *(const uint4*)&Bg[(size_t)row * D_ + kc + lcq * 8];
        }
        __syncthreads();
#pragma unroll
        for (int kk = 0; kk < 64; kk += 16) {
#pragma unroll
            for (int i = 0; i < 2; i++)
                wmma::load_matrix_sync(af[i], &sm[0][(wr * 32 + i * 16) * 72 + kk], 72);
#pragma unroll
            for (int j = 0; j < 4; j++)
                wmma::load_matrix_sync(bfr[j], &sm[1][(wc * 64 + j * 16) * 72 + kk], 72);
#pragma unroll
            for (int i = 0; i < 2; i++)
#pragma unroll
                for (int j = 0; j < 4; j++)
                    wmma::mma_sync(acc[i][j], af[i], bfr[j], acc[i][j]);
        }
        __syncthreads();
    }

    float* tile = (float*)&sm[0][0];
    for (int phase = 0; phase < 2; phase++) {
        if ((wr >> 1) == phase) {
            int lrr = (wr & 1) * 32;
#pragma unroll
            for (int i = 0; i < 2; i++)
#pragma unroll
                for (int j = 0; j < 4; j++)
                    wmma::store_matrix_sync(tile + (size_t)(lrr + i * 16) * 128 + wc * 64 + j * 16,
                                            acc[i][j], 128, wmma::mem_row_major);
        }
        __syncthreads();
        int rowoff = phase * 64;
        for (int e = threadIdx.x; e < 191 * 64; e += 256) {
            int dl = e >> 6;
            int t  = e & 63;
            int li = (dl > 127 ? dl - 127 : 0) + t;
            int lj = dl - li;
            if (li < 64 && lj >= 0 && lj < 128) {
                int gi = I0 + rowoff + li;
                int gj = J0 + lj;
                g_theta_bf[((size_t)b * NDIAG + (gi + gj)) * 1024 + gi] =
                    __float2bfloat16(tile[li * 128 + lj] * LOG2E);
            }
        }
        __syncthreads();
    }
}

// ---------------- 3) shuffle-wavefront DP with cp.async theta chunks ----------------
// CTA = 4 warps x 32 rows. In-warp neighbor via shfl_up. Warp->warp via smem boundary +
// cta flags; strip->strip via g_bound/g_prog. Theta: bf16, 32-diag chunks via cp.async,
// double-buffered in smem, issued 2 chunks (64 steps) ahead -> latency fully hidden.
__global__ void __launch_bounds__(128) dp_kernel(const float* __restrict__ gb,
                                                 float* __restrict__ out) {
    const int s = blockIdx.x, b = blockIdx.y;
    const int t = threadIdx.x, w = t >> 5, lane = t & 31;
    const int r0 = s * SROWS;
    const int w0 = r0 + w * 32;

    __shared__ float sB[3][1060];
    __shared__ int   sF[3];
    __shared__ float sA;
    __shared__ __align__(16) __nv_bfloat16 sTh[4][2][1024];  // [warp][buf][diag*32+lane]

    // ---- theta cp.async plumbing (per warp) ----
    // chunk c covers diags w0+32c .. w0+32c+31; each diag row = 64B (32 lanes bf16).
    const int qrow = lane >> 2;            // 0..7: diag row handled by this lane
    const char* thsrc = (const char*)g_theta_bf
                        + ((size_t)b * NDIAG + (size_t)w0) * 2048   // diag offset w0
                        + (size_t)w0 * 2                            // row offset w0
                        + (size_t)(lane & 3) * 16;
    unsigned int sdst = (unsigned int)__cvta_generic_to_shared(&sTh[w][0][0])
                        + qrow * 64 + (lane & 3) * 16;

#define ISSUE_CHUNK(c)                                                     \
    do {                                                                   \
        unsigned int dB = sdst + (((c) & 1) ? 2048u : 0u);                 \
        const char* sp = thsrc + (size_t)(32 * (c) + qrow) * 2048;         \
        cpasync16(dB,            sp);                                      \
        cpasync16(dB + 8 * 64,   sp + 8 * 2048);                           \
        cpasync16(dB + 16 * 64,  sp + 16 * 2048);                          \
        cpasync16(dB + 24 * 64,  sp + 24 * 2048);                          \
        asm volatile("cp.async.commit_group;");                            \
    } while (0)

    ISSUE_CHUNK(0);
    ISSUE_CHUNK(1);

    for (int k = t; k < 3 * 1060; k += 128) (&sB[0][0])[k] = NEGW;
    if (t < 3) sF[t] = -1;
    if (t == 0) {
        float a = 0.f;
#pragma unroll
        for (int k = 0; k < 8; k++) a += g_gpart[b][k];
        sA = (a + gb[0]) * LOG2E;
    }
    __syncthreads();

    const float A = sA, A2 = A + A;

    const bool cs = (w > 0);
    const bool cg = (w == 0 && s > 0);
    const bool ps = (w < 3);
    const bool pg = (w == 3 && s < STRIPS - 1);

    const float* sIn = sB[(w > 0) ? (w - 1) : 0];
    const int*   fIn = &sF[(w > 0) ? (w - 1) : 0];
    float* sOut = sB[(w < 3) ? w : 0];
    int*   fOut = &sF[(w < 3) ? w : 0];
    const float* gsrc = &g_bound[b][(s > 0) ? (s - 1) : 0][0];
    const int*   gfin = &g_prog[b][(s > 0) ? (s - 1) : 0];
    float* gdst  = &g_bound[b][s][0];
    int*   gfout = &g_prog[b][s];
    const int bend = w0 + 1022;

    float bufA = NEGW, bufB = NEGW;
    int gcache = -0x7FFFFFF0;
    int scache = -0x7FFFFFF0;

    auto gfetch = [&](int c16) -> float {
        int basei = w0 + 16 * c16 - 1;
        float v = NEGW;
        if (basei <= bend) {
            int tgt = min(basei + 15, bend);
            while (gcache < tgt) gcache = ld_acq(gfin);
            int d = basei + lane;
            if (lane < 16 && d <= bend) v = __ldcg(gsrc + d);
        }
        return v;
    };

    float bnd = NEGW;
    if (cg) {
        bufA = gfetch(0);
        bnd = __shfl_sync(0xffffffffu, bufA, 0);
    }

    float my_prev = NEGW;
    float nb_prev = (s == 0 && w == 0 && lane == 0) ? 0.0f : NEGW;

#define DP_MATH(P)                                                          \
    {                                                                       \
        float nb = __shfl_up_sync(0xffffffffu, my_prev, 1);                 \
        if (lane == 0) nb = bnd;                                            \
        float h  = fmaxf(nb, my_prev);                                      \
        float l  = fminf(nb, my_prev);                                      \
        float m  = fmaxf(h + A, nb_prev);                                   \
        float lo = fminf(l + A, nb_prev);                                   \
        float mid = ((h + l) + A2) + (nb_prev - m) - lo;                    \
        float sf = 1.0f + ex2f_(lo - m) + ex2f_(mid - m);                   \
        float val = (thv + m) + lg2f_(sf);                                  \
        val = ((unsigned)((P) - lane) <= 1023u) ? val : NEGW;               \
        nb_prev = nb;                                                       \
        my_prev = val;                                                      \
    }

#define DP_STEP(P, O)                                                       \
    {                                                                       \
        float bnew;                                                         \
        if (cs) bnew = sIn[(P) + 1];                                        \
        else if (cg) {                                                      \
            int pn = (P) + 1;                                               \
            float bsel = ((pn >> 4) & 1) ? bufB : bufA;                     \
            bnew = __shfl_sync(0xffffffffu, bsel, pn & 15);                 \
        } else bnew = NEGW;                                                 \
        float thn = ((O) < 31) ? __bfloat162float(tb[((O) + 1) * 32 + lane]) : 0.0f; \
        DP_MATH(P)                                                          \
        if (ps && lane == 31) {                                             \
            if ((unsigned)((P) - 31) <= 1023u) sOut[(P) - 31] = my_prev;    \
            if (((P) & 7) == 7) st_rel_cta(fOut, (P) - 31);                 \
        }                                                                   \
        if (pg && lane == 31) {                                             \
            if ((unsigned)((P) - 31) <= 1023u) __stcg(gdst + w0 + (P), my_prev); \
            if (((P) & 7) == 7) st_rel(gfout, w0 + (P));                    \
        }                                                                   \
        bnd = bnew; thv = thn;                                              \
    }

    // ---- main: 32 chunks of 32 steps (p = 0..1023) ----
    for (int c = 0; c < 32; c++) {
        asm volatile("cp.async.wait_group 1;");
        __syncwarp();
        const __nv_bfloat16* tb = &sTh[w][c & 1][0];
        float thv = __bfloat162float(tb[lane]);
        for (int sc = 0; sc < 4; sc++) {
            int p0s = 32 * c + 8 * sc;
            if (cs) {
                int tgt = min(p0s + 8, 1023);
                while (scache < tgt) scache = ld_acq_cta(fIn);
                if (p0s == 0) bnd = sIn[0];
            }
            if (cg && ((p0s & 15) == 0)) {
                int c16 = p0s >> 4;
                float v = gfetch(c16 + 1);
                if ((c16 + 1) & 1) bufB = v; else bufA = v;
            }
#pragma unroll
            for (int k = 0; k < 8; k++) {
                int o = 8 * sc + k;
                DP_STEP(p0s + k, o)
            }
        }
        ISSUE_CHUNK(c + 2);   // beyond-NDIAG reads land in pad; consumed slots always real
    }
    // ---- tail: chunk 32, steps p = 1024..1054 (31 steps) ----
    {
        asm volatile("cp.async.wait_group 1;");
        __syncwarp();
        const __nv_bfloat16* tb = &sTh[w][0][0];
        float thv = __bfloat162float(tb[lane]);
        if (cs) { while (scache < 1023) scache = ld_acq_cta(fIn); }
        for (int sc = 0; sc < 3; sc++) {
            int p0s = 1024 + 8 * sc;
#pragma unroll
            for (int k = 0; k < 8; k++) {
                int o = 8 * sc + k;
                DP_STEP(p0s + k, o)
            }
        }
#pragma unroll
        for (int k = 0; k < 7; k++) {
            int o = 24 + k;
            DP_STEP(1048 + k, o)
        }
    }
#undef DP_STEP
#undef DP_MATH
#undef ISSUE_CHUNK

    if (ps && lane == 31) st_rel_cta(fOut, 4096);
    if (pg && lane == 31) st_rel(gfout, 0x7FFFFFF0);

    if (s == STRIPS - 1 && w == 3 && lane == 31) out[b] = my_prev * LN2;
}

// ---------------- launch ----------------
extern "C" void kernel_launch(void* const* d_in, const int* in_sizes, int n_in,
                              void* d_out, int out_size) {
    (void)in_sizes; (void)n_in; (void)out_size;
    const float* zx = (const float*)d_in[0];
    const float* zy = (const float*)d_in[1];
    const float* gw = (const float*)d_in[2];
    const float* gb = (const float*)d_in[3];
    float* out = (float*)d_out;

    convgap_kernel<<<dim3(8, B_), 512>>>(zx, zy, gw);
    gemm_kernel<<<dim3(8, 8, B_), 256>>>();
    dp_kernel<<<dim3(STRIPS, B_), 128>>>(gb, out);
}

// round 8
// speedup vs baseline: 1.2281x; 1.0030x over previous
#include <cuda_runtime.h>
#include <cuda_bf16.h>
#include <mma.h>
#include <cstdint>

using namespace nvcuda;

#define B_    16
#define N_    1024
#define M_    1024
#define D_    512
#define NDIAG 2047
#define LOG2E 1.4426950408889634f
#define LN2   0.6931471805599453f
#define NEGW  -1.0e9f
#define STRIPS 8

// ---------------- device scratch ----------------
__device__ __nv_bfloat16 g_zx[(size_t)B_ * N_ * D_];
__device__ __nv_bfloat16 g_zy[(size_t)B_ * M_ * D_];
// theta in bf16, diag-major [b][d][i], pre-scaled by log2e; +128 diag global pad
__device__ __nv_bfloat16 g_theta_bf[((size_t)B_ * NDIAG + 128) * 1024];
__device__ float g_gpart[B_][8];
__device__ float g_bound[B_][2048];   // single CTA0->CTA1 boundary per batch (by global diag)
__device__ int   g_prog[B_][STRIPS];  // [b][0] used as the link flag (reset by convgap)

// ---------------- intrinsics ----------------
__device__ __forceinline__ float ex2f_(float x) {
    float y; asm("ex2.approx.ftz.f32 %0, %1;" : "=f"(y) : "f"(x)); return y;
}
__device__ __forceinline__ float lg2f_(float x) {
    float y; asm("lg2.approx.ftz.f32 %0, %1;" : "=f"(y) : "f"(x)); return y;
}
__device__ __forceinline__ int ld_acq(const int* p) {
    int v; asm volatile("ld.acquire.gpu.b32 %0, [%1];" : "=r"(v) : "l"(p) : "memory"); return v;
}
__device__ __forceinline__ void st_rel(int* p, int v) {
    asm volatile("st.release.gpu.b32 [%0], %1;" :: "l"(p), "r"(v) : "memory");
}
__device__ __forceinline__ int ld_acq_cta(const int* p) {
    int v; asm volatile("ld.acquire.cta.b32 %0, [%1];" : "=r"(v) : "l"(p) : "memory"); return v;
}
__device__ __forceinline__ void st_rel_cta(int* p, int v) {
    asm volatile("st.release.cta.b32 [%0], %1;" :: "l"(p), "r"(v) : "memory");
}
__device__ __forceinline__ void cpasync16(unsigned int dst, const void* src) {
    asm volatile("cp.async.cg.shared.global [%0], [%1], 16;" :: "r"(dst), "l"(src));
}

// soft-max merge of (u+A, g, f+A) in log2 domain, plus theta
__device__ __forceinline__ float cellf(float u, float g, float f,
                                       float A, float A2, float th) {
    float h  = fmaxf(u, f);
    float l  = fminf(u, f);
    float m  = fmaxf(h + A, g);
    float lo = fminf(l + A, g);
    float sum = (u + f) + (A2 + g);
    float mid = (sum - m) - lo;
    float e1 = ex2f_(lo - m);
    float e2 = ex2f_(mid - m);
    float r  = lg2f_((1.0f + e1) + e2);
    return (th + m) + r;
}

// ---------------- 1) fused fp32->bf16 convert + gap partial reduce ----------------
__global__ void __launch_bounds__(512) convgap_kernel(const float* __restrict__ zx,
                                                      const float* __restrict__ zy,
                                                      const float* __restrict__ gw) {
    int blk = blockIdx.x;
    int b   = blockIdx.y;
    int c   = threadIdx.x;
    if (blk == 0 && b == 0 && c < B_ * STRIPS) ((int*)g_prog)[c] = -1;

    size_t base = ((size_t)b * N_ + (size_t)blk * 128) * D_ + c;
    const float* px = zx + base;
    const float* py = zy + base;
    __nv_bfloat16* qx = g_zx + base;
    __nv_bfloat16* qy = g_zy + base;
    float sx = 0.f, sy = 0.f;
#pragma unroll 4
    for (int r = 0; r < 128; r++) {
        float vx = px[(size_t)r * D_];
        float vy = py[(size_t)r * D_];
        qx[(size_t)r * D_] = __float2bfloat16(vx);
        qy[(size_t)r * D_] = __float2bfloat16(vy);
        sx += vx; sy += vy;
    }
    float v = sx * (1.0f / N_) * gw[c] + sy * (1.0f / M_) * gw[512 + c];
    __shared__ float red[512];
    red[c] = v;
    __syncthreads();
    for (int st = 256; st > 0; st >>= 1) {
        if (c < st) red[c] += red[c + st];
        __syncthreads();
    }
    if (c == 0) g_gpart[b][blk] = red[0];
}

// ---------------- 2) GEMM theta = zx @ zy^T, bf16 WMMA, smem staged, bf16 diag epilogue ----
__global__ void __launch_bounds__(256) gemm_kernel() {
    __shared__ __align__(16) __nv_bfloat16 sm[2][128 * 72];

    int b  = blockIdx.z;
    int I0 = blockIdx.y * 128;
    int J0 = blockIdx.x * 128;
    const __nv_bfloat16* Ag = g_zx + ((size_t)b * N_ + I0) * D_;
    const __nv_bfloat16* Bg = g_zy + ((size_t)b * M_ + J0) * D_;

    int warpId = threadIdx.x >> 5;
    int wr = warpId & 3;
    int wc = warpId >> 2;

    wmma::fragment<wmma::accumulator, 16, 16, 16, float> acc[2][4];
#pragma unroll
    for (int i = 0; i < 2; i++)
#pragma unroll
        for (int j = 0; j < 4; j++) wmma::fill_fragment(acc[i][j], 0.0f);

    wmma::fragment<wmma::matrix_a, 16, 16, 16, __nv_bfloat16, wmma::row_major> af[2];
    wmma::fragment<wmma::matrix_b, 16, 16, 16, __nv_bfloat16, wmma::col_major> bfr[4];

    int lr  = threadIdx.x >> 3;
    int lcq = threadIdx.x & 7;

    for (int kc = 0; kc < D_; kc += 64) {
#pragma unroll
        for (int p = 0; p < 4; p++) {
            int row = lr + p * 32;
            *(uint4*)&sm[0][row * 72 + lcq * 8] =
                *(const uint4*)&Ag[(size_t)row * D_ + kc + lcq * 8];
            *(uint4*)&sm[1][row * 72 + lcq * 8] =
                *(const uint4*)&Bg[(size_t)row * D_ + kc + lcq * 8];
        }
        __syncthreads();
#pragma unroll
        for (int kk = 0; kk < 64; kk += 16) {
#pragma unroll
            for (int i = 0; i < 2; i++)
                wmma::load_matrix_sync(af[i], &sm[0][(wr * 32 + i * 16) * 72 + kk], 72);
#pragma unroll
            for (int j = 0; j < 4; j++)
                wmma::load_matrix_sync(bfr[j], &sm[1][(wc * 64 + j * 16) * 72 + kk], 72);
#pragma unroll
            for (int i = 0; i < 2; i++)
#pragma unroll
                for (int j = 0; j < 4; j++)
                    wmma::mma_sync(acc[i][j], af[i], bfr[j], acc[i][j]);
        }
        __syncthreads();
    }

    float* tile = (float*)&sm[0][0];
    for (int phase = 0; phase < 2; phase++) {
        if ((wr >> 1) == phase) {
            int lrr = (wr & 1) * 32;
#pragma unroll
            for (int i = 0; i < 2; i++)
#pragma unroll
                for (int j = 0; j < 4; j++)
                    wmma::store_matrix_sync(tile + (size_t)(lrr + i * 16) * 128 + wc * 64 + j * 16,
                                            acc[i][j], 128, wmma::mem_row_major);
        }
        __syncthreads();
        int rowoff = phase * 64;
        for (int e = threadIdx.x; e < 191 * 64; e += 256) {
            int dl = e >> 6;
            int t  = e & 63;
            int li = (dl > 127 ? dl - 127 : 0) + t;
            int lj = dl - li;
            if (li < 64 && lj >= 0 && lj < 128) {
                int gi = I0 + rowoff + li;
                int gj = J0 + lj;
                g_theta_bf[((size_t)b * NDIAG + (gi + gj)) * 1024 + gi] =
                    __float2bfloat16(tile[li * 128 + lj] * LOG2E);
            }
        }
        __syncthreads();
    }
}

// ---------------- 3) wavefront DP: 4 rows/thread, 128 rows/warp, 2 CTAs/batch ----------------
// Warp = 128 rows (lane owns 4 consecutive). In-warp neighbor via one shfl/step.
// Warp->warp via smem boundary + cta flags (8-diag granularity); CTA0->CTA1 via
// g_bound/g_prog with 32-diag register chunks prefetched one block ahead.
// Theta: bf16, 16-diag chunks via cp.async double-buffered (2 ahead).
__global__ void __launch_bounds__(128) dp_kernel(const float* __restrict__ gb,
                                                 float* __restrict__ out) {
    const int half = blockIdx.x;           // 0: rows 0..511, 1: rows 512..1023
    const int b    = blockIdx.y;
    const int t = threadIdx.x, w = t >> 5, lane = t & 31;
    const int row0w = half * 512 + w * 128;   // warp's first global row
    const int rbase = lane * 4;               // thread's first row within warp

    __shared__ __align__(16) __nv_bfloat16 sTh[4][2][2048];  // [warp][buf][16 diag * 128 row]
    __shared__ float sB[3][1184];
    __shared__ int   sF[3];
    __shared__ float sA;

    // ---- theta cp.async plumbing (per warp): chunk c = local diags 16c..16c+15 ----
    const char* thbase = (const char*)g_theta_bf
        + ((size_t)b * NDIAG + (size_t)row0w) * 2048 + (size_t)row0w * 2;
    const unsigned sdst0 = (unsigned)__cvta_generic_to_shared(&sTh[w][0][0])
        + (unsigned)(lane >> 4) * 256u + (unsigned)(lane & 15) * 16u;
    const char* thlane = thbase + (size_t)(lane >> 4) * 2048 + (size_t)(lane & 15) * 16;

#define ISSUE_CHUNK(c)                                                      \
    do {                                                                    \
        unsigned db = sdst0 + (((c) & 1) ? 4096u : 0u);                     \
        const char* sp = thlane + (size_t)(16 * (c)) * 2048;                \
        _Pragma("unroll")                                                   \
        for (int k8 = 0; k8 < 8; k8++)                                      \
            cpasync16(db + (unsigned)k8 * 512u, sp + (size_t)k8 * 4096);    \
        asm volatile("cp.async.commit_group;");                             \
    } while (0)

    ISSUE_CHUNK(0);
    ISSUE_CHUNK(1);

    for (int k = t; k < 3 * 1184; k += 128) (&sB[0][0])[k] = NEGW;
    if (t < 3) sF[t] = -1;
    if (t == 0) {
        float a = 0.f;
#pragma unroll
        for (int k = 0; k < 8; k++) a += g_gpart[b][k];
        sA = (a + gb[0]) * LOG2E;
    }
    __syncthreads();

    const float A = sA, A2 = A + A;

    const bool cs = (w > 0);                    // consume smem boundary
    const bool cg = (w == 0 && half == 1);      // consume global boundary
    const bool ps = (w < 3);                    // produce smem boundary
    const bool pg = (w == 3 && half == 0);      // produce global boundary

    const float* sIn = sB[(w > 0) ? (w - 1) : 0];
    const int*   fIn = &sF[(w > 0) ? (w - 1) : 0];
    float* sOut = sB[(w < 3) ? w : 0];
    int*   fOut = &sF[(w < 3) ? w : 0];
    const float* gsrc = &g_bound[b][0];
    float* gdstp = &g_bound[b][384];            // producer stores at diag 384 + P
    int*   gflag = &g_prog[b][0];

    int gcache = -0x40000000, scache = -1;
    float gb0 = NEGW, gb1 = NEGW;               // 32-diag boundary blocks (lane-held)

    // block c32 covers consumer steps q in [32c32, 32c32+31] -> boundary diag 511+q
    auto gfetch32 = [&](int c32) -> float {
        float v = NEGW;
        int qb = 32 * c32;
        if (qb <= 1023) {
            int tgt = min(511 + qb + 31, 1534);
            while (gcache < tgt) gcache = ld_acq(gflag);
            if (qb + lane <= 1023) v = __ldcg(gsrc + 511 + qb + lane);
        }
        return v;
    };
    if (cg) gb0 = gfetch32(0);

    // per-row DP state
    float pv0 = NEGW, pv1 = NEGW, pv2 = NEGW, pv3 = NEGW;   // values at diag p-1
    float q0 = NEGW, q1 = NEGW, q2 = NEGW;                   // rows 0..2 at diag p-2
    float nbp = (half == 0 && w == 0 && lane == 0) ? 0.0f : NEGW;  // neighbor at p-2

#define DP_STEP(P, O)                                                       \
    {                                                                       \
        uint2 tw = *(const uint2*)(tb + (O) * 128 + rbase);                 \
        float bnd;                                                          \
        if (cs) bnd = sIn[(P)];                                             \
        else if (cg) {                                                      \
            float bsel = (((P) >> 5) & 1) ? gb1 : gb0;                      \
            bnd = __shfl_sync(0xffffffffu, bsel, (P) & 31);                 \
        } else bnd = NEGW;                                                  \
        float nbr = __shfl_up_sync(0xffffffffu, pv3, 1);                    \
        float nb = (lane == 0) ? bnd : nbr;                                 \
        float t0 = __uint_as_float(tw.x << 16);                             \
        float t1 = __uint_as_float(tw.x & 0xffff0000u);                     \
        float t2 = __uint_as_float(tw.y << 16);                             \
        float t3 = __uint_as_float(tw.y & 0xffff0000u);                     \
        float v0 = cellf(nb,  nbp, pv0, A, A2, t0);                         \
        float v1 = cellf(pv0, q0,  pv1, A, A2, t1);                         \
        float v2 = cellf(pv1, q1,  pv2, A, A2, t2);                         \
        float v3 = cellf(pv2, q2,  pv3, A, A2, t3);                         \
        v0 = ((unsigned)((P) - (rbase + 0)) <= 1023u) ? v0 : NEGW;          \
        v1 = ((unsigned)((P) - (rbase + 1)) <= 1023u) ? v1 : NEGW;          \
        v2 = ((unsigned)((P) - (rbase + 2)) <= 1023u) ? v2 : NEGW;          \
        v3 = ((unsigned)((P) - (rbase + 3)) <= 1023u) ? v3 : NEGW;          \
        nbp = nb; q0 = pv0; q1 = pv1; q2 = pv2;                             \
        pv0 = v0; pv1 = v1; pv2 = v2; pv3 = v3;                             \
        if (lane == 31) {                                                   \
            int e = (P) - 127;                                              \
            if (ps) {                                                       \
                if ((unsigned)e <= 1023u) sOut[e] = v3;                     \
                if (((O) & 7) == 7) st_rel_cta(fOut, e);                    \
            }                                                               \
            if (pg) {                                                       \
                if ((unsigned)e <= 1023u) __stcg(gdstp + (P), v3);          \
                if (((O) & 7) == 7) st_rel(gflag, 384 + (P));               \
            }                                                               \
        }                                                                   \
    }

    int p = 0;
    for (int c = 0; c < 71; c++) {              // 71 full chunks: steps 0..1135
        asm volatile("cp.async.wait_group 1;");
        __syncwarp();
        const __nv_bfloat16* tb = &sTh[w][c & 1][0];
        if (cg && ((c & 1) == 0)) {
            int c32 = c >> 1;
            float v = gfetch32(c32 + 1);
            if ((c32 + 1) & 1) gb1 = v; else gb0 = v;
        }
#pragma unroll
        for (int blk = 0; blk < 2; blk++) {
            if (cs) {
                int tgt = min(p + 8, 1023);
                while (scache < tgt) scache = ld_acq_cta(fIn);
            }
#pragma unroll
            for (int k = 0; k < 8; k++) {
                DP_STEP(p, (blk * 8 + k))
                p++;
            }
        }
        ISSUE_CHUNK(c + 2);
    }
    // tail chunk 71: steps 1136..1150 (15 steps)
    {
        asm volatile("cp.async.wait_group 0;");
        __syncwarp();
        const __nv_bfloat16* tb = &sTh[w][71 & 1][0];
        if (cs) { while (scache < 1023) scache = ld_acq_cta(fIn); }
        if (cg) {   // steps >= 1136 have all boundary rows masked; keep regs defined
            gb0 = NEGW; gb1 = NEGW;
        }
#pragma unroll
        for (int k = 0; k < 8; k++) { DP_STEP(p, k) p++; }
#pragma unroll
        for (int k = 8; k < 15; k++) { DP_STEP(p, k) p++; }
    }
#undef DP_STEP
#undef ISSUE_CHUNK

    if (ps && lane == 31) st_rel_cta(fOut, 4096);
    if (pg && lane == 31) st_rel(gflag, 0x7FFFFFF0);

    // half 1, warp 3, lane 31, row 3 = global row 1023 at diag 2046 -> V[N][M]
    if (half == 1 && w == 3 && lane == 31) out[b] = pv3 * LN2;
}

// ---------------- launch ----------------
extern "C" void kernel_launch(void* const* d_in, const int* in_sizes, int n_in,
                              void* d_out, int out_size) {
    (void)in_sizes; (void)n_in; (void)out_size;
    const float* zx = (const float*)d_in[0];
    const float* zy = (const float*)d_in[1];
    const float* gw = (const float*)d_in[2];
    const float* gb = (const float*)d_in[3];
    float* out = (float*)d_out;

    convgap_kernel<<<dim3(8, B_), 512>>>(zx, zy, gw);
    gemm_kernel<<<dim3(8, 8, B_), 256>>>();
    dp_kernel<<<dim3(2, B_), 128>>>(gb, out);
}

// round 9
// speedup vs baseline: 1.3580x; 1.1058x over previous
#include <cuda_runtime.h>
#include <cuda_bf16.h>
#include <mma.h>
#include <cstdint>

using namespace nvcuda;

#define B_    16
#define N_    1024
#define M_    1024
#define D_    512
#define NDIAG 2047
#define LOG2E 1.4426950408889634f
#define LN2   0.6931471805599453f
#define NEGW  -1.0e9f
#define STRIPS 8

// DP geometry: 2 CTAs/batch, 8 warps/CTA, 64 rows/warp, 2 rows/lane
#define WSTEPS 1087           // 64 + 1023 steps per warp
#define NCHUNK 68             // 16-diag theta chunks (67 full + 15-step tail)
#define SB_LEN 1104           // per-link boundary array length (>= 1087, 16B-mult)
#define DYN_SMEM (32768 + 7 * SB_LEN * 4 + 32)

// ---------------- device scratch ----------------
__device__ __nv_bfloat16 g_zx[(size_t)B_ * N_ * D_];
__device__ __nv_bfloat16 g_zy[(size_t)B_ * M_ * D_];
// theta in bf16, diag-major [b][d][i], pre-scaled by log2e; +128 diag global pad
__device__ __nv_bfloat16 g_theta_bf[((size_t)B_ * NDIAG + 128) * 1024];
__device__ float g_gpart[B_][8];
__device__ float g_bound[B_][2048];   // CTA0->CTA1 boundary per batch (indexed by diag)
__device__ int   g_prog[B_][STRIPS];  // [b][0] = link flag (reset by convgap)

// ---------------- intrinsics ----------------
__device__ __forceinline__ float ex2f_(float x) {
    float y; asm("ex2.approx.ftz.f32 %0, %1;" : "=f"(y) : "f"(x)); return y;
}
__device__ __forceinline__ float lg2f_(float x) {
    float y; asm("lg2.approx.ftz.f32 %0, %1;" : "=f"(y) : "f"(x)); return y;
}
__device__ __forceinline__ int ld_acq(const int* p) {
    int v; asm volatile("ld.acquire.gpu.b32 %0, [%1];" : "=r"(v) : "l"(p) : "memory"); return v;
}
__device__ __forceinline__ void st_rel(int* p, int v) {
    asm volatile("st.release.gpu.b32 [%0], %1;" :: "l"(p), "r"(v) : "memory");
}
__device__ __forceinline__ int ld_acq_cta(const int* p) {
    int v; asm volatile("ld.acquire.cta.b32 %0, [%1];" : "=r"(v) : "l"(p) : "memory"); return v;
}
__device__ __forceinline__ void st_rel_cta(int* p, int v) {
    asm volatile("st.release.cta.b32 [%0], %1;" :: "l"(p), "r"(v) : "memory");
}
__device__ __forceinline__ void cpasync16(unsigned int dst, const void* src) {
    asm volatile("cp.async.cg.shared.global [%0], [%1], 16;" :: "r"(dst), "l"(src));
}

// soft-max merge of (u+A, g, f+A) in log2 domain, plus theta
__device__ __forceinline__ float cellf(float u, float g, float f,
                                       float A, float A2, float th) {
    float h  = fmaxf(u, f);
    float l  = fminf(u, f);
    float m  = fmaxf(h + A, g);
    float lo = fminf(l + A, g);
    float sum = (u + f) + (A2 + g);
    float mid = (sum - m) - lo;
    float e1 = ex2f_(lo - m);
    float e2 = ex2f_(mid - m);
    float r  = lg2f_((1.0f + e1) + e2);
    return (th + m) + r;
}

// ---------------- 1) fused fp32->bf16 convert + gap partial reduce ----------------
__global__ void __launch_bounds__(512) convgap_kernel(const float* __restrict__ zx,
                                                      const float* __restrict__ zy,
                                                      const float* __restrict__ gw) {
    int blk = blockIdx.x;
    int b   = blockIdx.y;
    int c   = threadIdx.x;
    if (blk == 0 && b == 0 && c < B_ * STRIPS) ((int*)g_prog)[c] = -1;

    size_t base = ((size_t)b * N_ + (size_t)blk * 128) * D_ + c;
    const float* px = zx + base;
    const float* py = zy + base;
    __nv_bfloat16* qx = g_zx + base;
    __nv_bfloat16* qy = g_zy + base;
    float sx = 0.f, sy = 0.f;
#pragma unroll 4
    for (int r = 0; r < 128; r++) {
        float vx = px[(size_t)r * D_];
        float vy = py[(size_t)r * D_];
        qx[(size_t)r * D_] = __float2bfloat16(vx);
        qy[(size_t)r * D_] = __float2bfloat16(vy);
        sx += vx; sy += vy;
    }
    float v = sx * (1.0f / N_) * gw[c] + sy * (1.0f / M_) * gw[512 + c];
    __shared__ float red[512];
    red[c] = v;
    __syncthreads();
    for (int st = 256; st > 0; st >>= 1) {
        if (c < st) red[c] += red[c + st];
        __syncthreads();
    }
    if (c == 0) g_gpart[b][blk] = red[0];
}

// ---------------- 2) GEMM theta = zx @ zy^T, bf16 WMMA, smem staged, bf16 diag epilogue ----
__global__ void __launch_bounds__(256) gemm_kernel() {
    __shared__ __align__(16) __nv_bfloat16 sm[2][128 * 72];

    int b  = blockIdx.z;
    int I0 = blockIdx.y * 128;
    int J0 = blockIdx.x * 128;
    const __nv_bfloat16* Ag = g_zx + ((size_t)b * N_ + I0) * D_;
    const __nv_bfloat16* Bg = g_zy + ((size_t)b * M_ + J0) * D_;

    int warpId = threadIdx.x >> 5;
    int wr = warpId & 3;
    int wc = warpId >> 2;

    wmma::fragment<wmma::accumulator, 16, 16, 16, float> acc[2][4];
#pragma unroll
    for (int i = 0; i < 2; i++)
#pragma unroll
        for (int j = 0; j < 4; j++) wmma::fill_fragment(acc[i][j], 0.0f);

    wmma::fragment<wmma::matrix_a, 16, 16, 16, __nv_bfloat16, wmma::row_major> af[2];
    wmma::fragment<wmma::matrix_b, 16, 16, 16, __nv_bfloat16, wmma::col_major> bfr[4];

    int lr  = threadIdx.x >> 3;
    int lcq = threadIdx.x & 7;

    for (int kc = 0; kc < D_; kc += 64) {
#pragma unroll
        for (int p = 0; p < 4; p++) {
            int row = lr + p * 32;
            *(uint4*)&sm[0][row * 72 + lcq * 8] =
                *(const uint4*)&Ag[(size_t)row * D_ + kc + lcq * 8];
            *(uint4*)&sm[1][row * 72 + lcq * 8] =
                *(const uint4*)&Bg[(size_t)row * D_ + kc + lcq * 8];
        }
        __syncthreads();
#pragma unroll
        for (int kk = 0; kk < 64; kk += 16) {
#pragma unroll
            for (int i = 0; i < 2; i++)
                wmma::load_matrix_sync(af[i], &sm[0][(wr * 32 + i * 16) * 72 + kk], 72);
#pragma unroll
            for (int j = 0; j < 4; j++)
                wmma::load_matrix_sync(bfr[j], &sm[1][(wc * 64 + j * 16) * 72 + kk], 72);
#pragma unroll
            for (int i = 0; i < 2; i++)
#pragma unroll
                for (int j = 0; j < 4; j++)
                    wmma::mma_sync(acc[i][j], af[i], bfr[j], acc[i][j]);
        }
        __syncthreads();
    }

    float* tile = (float*)&sm[0][0];
    for (int phase = 0; phase < 2; phase++) {
        if ((wr >> 1) == phase) {
            int lrr = (wr & 1) * 32;
#pragma unroll
            for (int i = 0; i < 2; i++)
#pragma unroll
                for (int j = 0; j < 4; j++)
                    wmma::store_matrix_sync(tile + (size_t)(lrr + i * 16) * 128 + wc * 64 + j * 16,
                                            acc[i][j], 128, wmma::mem_row_major);
        }
        __syncthreads();
        int rowoff = phase * 64;
        for (int e = threadIdx.x; e < 191 * 64; e += 256) {
            int dl = e >> 6;
            int t  = e & 63;
            int li = (dl > 127 ? dl - 127 : 0) + t;
            int lj = dl - li;
            if (li < 64 && lj >= 0 && lj < 128) {
                int gi = I0 + rowoff + li;
                int gj = J0 + lj;
                g_theta_bf[((size_t)b * NDIAG + (gi + gj)) * 1024 + gi] =
                    __float2bfloat16(tile[li * 128 + lj] * LOG2E);
            }
        }
        __syncthreads();
    }
}

// ---------------- 3) wavefront DP: 2 rows/lane, 64 rows/warp, 8 warps/CTA, 2 CTAs/batch ----
// 2 warps per SMSP interleave issue slots. Warp->warp via dynamic-smem boundary arrays +
// cta flags (8-diag granularity). CTA0->CTA1 via g_bound/g_prog, 32-diag register chunks.
// Theta: bf16, 16-diag 2KB chunks via cp.async double-buffered (2 ahead).
__global__ void __launch_bounds__(256) dp_kernel(const float* __restrict__ gb,
                                                 float* __restrict__ out) {
    const int half = blockIdx.x;               // 0: rows 0..511, 1: rows 512..1023
    const int b    = blockIdx.y;
    const int t = threadIdx.x, w = t >> 5, lane = t & 31;
    const int row0w = half * 512 + w * 64;     // warp's first global row
    const int rbase = lane * 2;                // lane's first local row

    extern __shared__ char smem_dyn[];
    __nv_bfloat16* sThAll = (__nv_bfloat16*)smem_dyn;              // 8 warps x 2 bufs x 2KB
    float* sBall = (float*)(smem_dyn + 32768);                     // 7 x SB_LEN floats
    int*   sF    = (int*)(smem_dyn + 32768 + 7 * SB_LEN * 4);      // 7 flags
    float* sAp   = (float*)(smem_dyn + 32768 + 7 * SB_LEN * 4 + 28);

    // ---- theta cp.async plumbing: chunk c = local diags 16c..16c+15, 2KB (64 rows/diag) ----
    const char* thw = (const char*)g_theta_bf
        + ((size_t)b * NDIAG + (size_t)row0w) * 2048 + (size_t)row0w * 2;
    const unsigned sdstW = (unsigned)__cvta_generic_to_shared(smem_dyn) + (unsigned)w * 4096u;

#define ISSUE_CHUNK(c)                                                        \
    do {                                                                      \
        unsigned db_ = sdstW + (((c) & 1) ? 2048u : 0u);                      \
        _Pragma("unroll")                                                     \
        for (int u4 = 0; u4 < 4; u4++) {                                      \
            int u_ = lane + 32 * u4;                                          \
            cpasync16(db_ + (unsigned)u_ * 16u,                               \
                      thw + (size_t)(16 * (c) + (u_ >> 3)) * 2048 + (u_ & 7) * 16); \
        }                                                                     \
        asm volatile("cp.async.commit_group;");                               \
    } while (0)

    ISSUE_CHUNK(0);
    ISSUE_CHUNK(1);

    for (int k = t; k < 7 * SB_LEN; k += 256) sBall[k] = NEGW;
    if (t < 7) sF[t] = -1;
    if (t == 0) {
        float a = 0.f;
#pragma unroll
        for (int k = 0; k < 8; k++) a += g_gpart[b][k];
        *sAp = (a + gb[0]) * LOG2E;
    }
    __syncthreads();

    const float A = *sAp, A2 = A + A;

    const bool cs = (w > 0);                   // consume smem boundary
    const bool cg = (w == 0 && half == 1);     // consume global boundary
    const bool ps = (w < 7);                   // produce smem boundary
    const bool pg = (w == 7 && half == 0);     // produce global boundary

    const float* sIn = sBall + (size_t)((w > 0) ? (w - 1) : 0) * SB_LEN;
    const int*   fIn = &sF[(w > 0) ? (w - 1) : 0];
    float* sOut = sBall + (size_t)((w < 7) ? w : 0) * SB_LEN;
    int*   fOut = &sF[(w < 7) ? w : 0];
    const float* gsrc = &g_bound[b][0];
    float* gdstp = &g_bound[b][448];           // producer (row0w=448) stores diag 448+P
    int*   gflag = &g_prog[b][0];

    int gcache = -0x40000000, scache = -1;
    float gb0 = NEGW, gb1 = NEGW;              // 32-step global boundary blocks

    // block c32 covers consumer steps q in [32c32, 32c32+31] -> boundary diag 511+q
    auto gfetch32 = [&](int c32) -> float {
        float v = NEGW;
        int qb = 32 * c32;
        if (qb <= 1023) {
            int tgt = min(511 + qb + 31, 1534);
            while (gcache < tgt) gcache = ld_acq(gflag);
            if (qb + lane <= 1023) v = __ldcg(gsrc + 511 + qb + lane);
        }
        return v;
    };
    if (cg) gb0 = gfetch32(0);

    // per-lane DP state (rows rbase, rbase+1)
    float pv0 = NEGW, pv1 = NEGW;              // values at diag p-1
    float q0 = NEGW;                            // row0 value at diag p-2
    float nbp = (half == 0 && w == 0 && lane == 0) ? 0.0f : NEGW;  // neighbor at p-2

#define DP_STEP(P, O)                                                        \
    {                                                                        \
        unsigned tw = *(const unsigned*)((const char*)tb + (O) * 128 + lane * 4); \
        float bnd;                                                           \
        if (cs) bnd = sIn[(P)];                                              \
        else if (cg) {                                                       \
            float bsel = (((P) >> 5) & 1) ? gb1 : gb0;                       \
            bnd = __shfl_sync(0xffffffffu, bsel, (P) & 31);                  \
        } else bnd = NEGW;                                                   \
        float nbr = __shfl_up_sync(0xffffffffu, pv1, 1);                     \
        float nb = (lane == 0) ? bnd : nbr;                                  \
        float t0 = __uint_as_float(tw << 16);                                \
        float t1 = __uint_as_float(tw & 0xffff0000u);                        \
        float v0 = cellf(nb,  nbp, pv0, A, A2, t0);                          \
        float v1 = cellf(pv0, q0,  pv1, A, A2, t1);                          \
        v0 = ((unsigned)((P) - (rbase + 0)) <= 1023u) ? v0 : NEGW;           \
        v1 = ((unsigned)((P) - (rbase + 1)) <= 1023u) ? v1 : NEGW;           \
        nbp = nb; q0 = pv0;                                                  \
        pv0 = v0; pv1 = v1;                                                  \
        if (lane == 31) {                                                    \
            int e = (P) - 63;                                                \
            if (ps) {                                                        \
                if ((unsigned)e <= 1023u) sOut[e] = v1;                      \
                if (((O) & 7) == 7) st_rel_cta(fOut, e);                     \
            }                                                                \
            if (pg) {                                                        \
                if ((unsigned)e <= 1023u) __stcg(gdstp + (P), v1);           \
                if (((O) & 7) == 7) st_rel(gflag, 448 + (P));                \
            }                                                                \
        }                                                                    \
    }

    int p = 0;
    for (int c = 0; c < 67; c++) {             // 67 full chunks: steps 0..1071
        asm volatile("cp.async.wait_group 1;");
        __syncwarp();
        const __nv_bfloat16* tb = (const __nv_bfloat16*)(smem_dyn + w * 4096 + (c & 1) * 2048);
        if (cg && ((c & 1) == 0)) {
            int c32 = c >> 1;
            float v = gfetch32(c32 + 1);
            if ((c32 + 1) & 1) gb1 = v; else gb0 = v;
        }
#pragma unroll
        for (int blk = 0; blk < 2; blk++) {
            if (cs) {
                int tgt = min(p + 7, 1023);
                while (scache < tgt) scache = ld_acq_cta(fIn);
            }
#pragma unroll
            for (int k = 0; k < 8; k++) {
                DP_STEP(p, (blk * 8 + k))
                p++;
            }
        }
        ISSUE_CHUNK(c + 2);
    }
    // tail chunk 67: steps 1072..1086 (15 steps)
    {
        asm volatile("cp.async.wait_group 1;");
        __syncwarp();
        const __nv_bfloat16* tb = (const __nv_bfloat16*)(smem_dyn + w * 4096 + (67 & 1) * 2048);
        if (cs) { while (scache < 1023) scache = ld_acq_cta(fIn); }
        if (cg) { gb0 = NEGW; gb1 = NEGW; }    // all boundary rows masked past q=1023
#pragma unroll
        for (int k = 0; k < 8; k++) { DP_STEP(p, k) p++; }
#pragma unroll
        for (int k = 8; k < 15; k++) { DP_STEP(p, k) p++; }
    }
#undef DP_STEP
#undef ISSUE_CHUNK

    if (ps && lane == 31) st_rel_cta(fOut, 4096);
    if (pg && lane == 31) st_rel(gflag, 0x7FFFFFF0);

    // half 1, warp 7, lane 31, row 1 = global row 1023 at diag 2046 -> V[N][M]
    if (half == 1 && w == 7 && lane == 31) out[b] = pv1 * LN2;
}

// ---------------- launch ----------------
extern "C" void kernel_launch(void* const* d_in, const int* in_sizes, int n_in,
                              void* d_out, int out_size) {
    (void)in_sizes; (void)n_in; (void)out_size;
    const float* zx = (const float*)d_in[0];
    const float* zy = (const float*)d_in[1];
    const float* gw = (const float*)d_in[2];
    const float* gb = (const float*)d_in[3];
    float* out = (float*)d_out;

    cudaFuncSetAttribute(dp_kernel, cudaFuncAttributeMaxDynamicSharedMemorySize, DYN_SMEM);

    convgap_kernel<<<dim3(8, B_), 512>>>(zx, zy, gw);
    gemm_kernel<<<dim3(8, 8, B_), 256>>>();
    dp_kernel<<<dim3(2, B_), 256, DYN_SMEM>>>(gb, out);
}